// round 16
// baseline (speedup 1.0000x reference)
#include <cuda_runtime.h>

// Unitary gate on wires {5,13} of a 26-wire register (target bits 20 and 12).
// out[b + off] = U[4x4] @ x[b + off], off ∈ {0, 2^12, 2^20, 2^20+2^12}.
//
// FINAL KERNEL (measured optimum across 15 rounds; 5 repeat samples).
//
// DRAM-bound streaming problem: 512 MB minimum traffic (256 MB read +
// 256 MB write, each byte touched exactly once). Runs at the HW-measured
// B300 LTS ceiling: best run 6.53 TB/s / DRAM 82.5% / 73.6 us ncu.
// Run-to-run noise band (same binary): harness 81.0-82.4 us (DVFS).
//
// Design (each element A/B-measured):
//  - 4 x float4 per thread (one per gate-input stream), front-batched:
//    32 regs = full RF at 2048 threads/SM -> max chip-wide MLP. Wider
//    unrolling / persistence / serialized groups all lost 5-30%.
//  - Bit-insertion indexing: all 8 streams perfectly coalesced
//    (low 12 bits of the flat index are thread-contiguous).
//  - U via 4 x LDG.128 broadcast (halves L1tex wavefront queue depth
//    vs 16 scalar loads; -2.6 us).
//  - BLOCK=512: best of {256, 512, 1024} (row-burst locality vs residency).
//  - __ldcs/__stcs streaming hints (neutral but harmless; __stwt neutral).

static constexpr unsigned REST    = 1u << 24;   // rest-index count
static constexpr unsigned THREADS = REST / 4;   // 4 consecutive rest positions / thread

static constexpr unsigned OFF12_V4 = (1u << 12) >> 2;  // stream offsets in float4 units
static constexpr unsigned OFF20_V4 = (1u << 20) >> 2;

static constexpr unsigned BLOCK = 512;

__global__ __launch_bounds__(BLOCK, 4)
void unitary_gate_kernel(const float4* __restrict__ x4,
                         const float4* __restrict__ U4,
                         float4*       __restrict__ o4)
{
    unsigned r  = blockIdx.x * BLOCK + threadIdx.x;        // 0 .. 2^22-1
    unsigned rr = r << 2;                                  // rest index (multiple of 4)

    // Insert zero bits at positions 12 and 20 of the flat amplitude index:
    //   rr bits [0..11]  -> base bits [0..11]
    //   rr bits [12..18] -> base bits [13..19]
    //   rr bits [19..23] -> base bits [21..25]
    unsigned base = (rr & 0x00000FFFu)
                  | ((rr & 0x0007F000u) << 1)
                  | ((rr & 0x00F80000u) << 2);
    unsigned i0 = base >> 2;  // float4 index (base is a multiple of 4)

    // Gate matrix: 4 x 128-bit broadcast loads (L1/L2-resident).
    float4 u0 = __ldg(U4 + 0);   // row 0
    float4 u1 = __ldg(U4 + 1);   // row 1
    float4 u2 = __ldg(U4 + 2);   // row 2
    float4 u3 = __ldg(U4 + 3);   // row 3

    // Front-batched streaming loads (MLP=4, evict-first).
    float4 s0 = __ldcs(x4 + i0);
    float4 s1 = __ldcs(x4 + i0 + OFF12_V4);
    float4 s2 = __ldcs(x4 + i0 + OFF20_V4);
    float4 s3 = __ldcs(x4 + i0 + OFF20_V4 + OFF12_V4);

    float4 d0, d1, d2, d3;
    d0.x = u0.x*s0.x + u0.y*s1.x + u0.z*s2.x + u0.w*s3.x;
    d0.y = u0.x*s0.y + u0.y*s1.y + u0.z*s2.y + u0.w*s3.y;
    d0.z = u0.x*s0.z + u0.y*s1.z + u0.z*s2.z + u0.w*s3.z;
    d0.w = u0.x*s0.w + u0.y*s1.w + u0.z*s2.w + u0.w*s3.w;

    d1.x = u1.x*s0.x + u1.y*s1.x + u1.z*s2.x + u1.w*s3.x;
    d1.y = u1.x*s0.y + u1.y*s1.y + u1.z*s2.y + u1.w*s3.y;
    d1.z = u1.x*s0.z + u1.y*s1.z + u1.z*s2.z + u1.w*s3.z;
    d1.w = u1.x*s0.w + u1.y*s1.w + u1.z*s2.w + u1.w*s3.w;

    d2.x = u2.x*s0.x + u2.y*s1.x + u2.z*s2.x + u2.w*s3.x;
    d2.y = u2.x*s0.y + u2.y*s1.y + u2.z*s2.y + u2.w*s3.y;
    d2.z = u2.x*s0.z + u2.y*s1.z + u2.z*s2.z + u2.w*s3.z;
    d2.w = u2.x*s0.w + u2.y*s1.w + u2.z*s2.w + u2.w*s3.w;

    d3.x = u3.x*s0.x + u3.y*s1.x + u3.z*s2.x + u3.w*s3.x;
    d3.y = u3.x*s0.y + u3.y*s1.y + u3.z*s2.y + u3.w*s3.y;
    d3.z = u3.x*s0.z + u3.y*s1.z + u3.z*s2.z + u3.w*s3.z;
    d3.w = u3.x*s0.w + u3.y*s1.w + u3.z*s2.w + u3.w*s3.w;

    __stcs(o4 + i0,                       d0);
    __stcs(o4 + i0 + OFF12_V4,            d1);
    __stcs(o4 + i0 + OFF20_V4,            d2);
    __stcs(o4 + i0 + OFF20_V4 + OFF12_V4, d3);
}

extern "C" void kernel_launch(void* const* d_in, const int* in_sizes, int n_in,
                              void* d_out, int out_size)
{
    const float* x = (const float*)d_in[0];
    const float* U = (const float*)d_in[1];
    if (n_in >= 2 && in_sizes[0] == 16) {  // defensive: swapped order
        U = (const float*)d_in[0];
        x = (const float*)d_in[1];
    }
    float* out = (float*)d_out;

    const unsigned blocks = THREADS / BLOCK;  // 8192
    unitary_gate_kernel<<<blocks, BLOCK>>>(
        (const float4*)x, (const float4*)U, (float4*)out);
}

// round 17
// speedup vs baseline: 1.0008x; 1.0008x over previous
#include <cuda_runtime.h>

// Unitary gate on wires {5,13} of a 26-wire register (target bits 20 and 12).
// out[b + off] = U[4x4] @ x[b + off], off ∈ {0, 2^12, 2^20, 2^20+2^12}.
//
// FINAL KERNEL (measured optimum; 6 repeat samples confirm noise-floor).
//
// DRAM-bound streaming problem: 512 MB minimum traffic (256 MB read +
// 256 MB write, each byte touched exactly once). Runs at the HW-measured
// B300 LTS/DRAM ceiling for this mix: 6.2-6.53 TB/s, DRAM 78-82.5%
// active, 73.6-77.6 us ncu; harness 81.0-82.4 us (DVFS variance).
//
// Design (each element A/B-measured):
//  - 4 x float4 per thread (one per gate-input stream), front-batched:
//    32 regs = full RF at 2048 threads/SM -> max chip-wide MLP. Wider
//    unrolling / persistence / serialized groups all lost 5-30%.
//  - Bit-insertion indexing: all 8 streams perfectly coalesced
//    (low 12 bits of the flat index are thread-contiguous).
//  - U via 4 x LDG.128 broadcast (halves L1tex wavefront queue depth
//    vs 16 scalar loads; -2.6 us).
//  - BLOCK=512: best of {256, 512, 1024} (row-burst locality vs residency).
//  - __ldcs/__stcs streaming hints (neutral but harmless; __stwt neutral).

static constexpr unsigned REST    = 1u << 24;   // rest-index count
static constexpr unsigned THREADS = REST / 4;   // 4 consecutive rest positions / thread

static constexpr unsigned OFF12_V4 = (1u << 12) >> 2;  // stream offsets in float4 units
static constexpr unsigned OFF20_V4 = (1u << 20) >> 2;

static constexpr unsigned BLOCK = 512;

__global__ __launch_bounds__(BLOCK, 4)
void unitary_gate_kernel(const float4* __restrict__ x4,
                         const float4* __restrict__ U4,
                         float4*       __restrict__ o4)
{
    unsigned r  = blockIdx.x * BLOCK + threadIdx.x;        // 0 .. 2^22-1
    unsigned rr = r << 2;                                  // rest index (multiple of 4)

    // Insert zero bits at positions 12 and 20 of the flat amplitude index:
    //   rr bits [0..11]  -> base bits [0..11]
    //   rr bits [12..18] -> base bits [13..19]
    //   rr bits [19..23] -> base bits [21..25]
    unsigned base = (rr & 0x00000FFFu)
                  | ((rr & 0x0007F000u) << 1)
                  | ((rr & 0x00F80000u) << 2);
    unsigned i0 = base >> 2;  // float4 index (base is a multiple of 4)

    // Gate matrix: 4 x 128-bit broadcast loads (L1/L2-resident).
    float4 u0 = __ldg(U4 + 0);   // row 0
    float4 u1 = __ldg(U4 + 1);   // row 1
    float4 u2 = __ldg(U4 + 2);   // row 2
    float4 u3 = __ldg(U4 + 3);   // row 3

    // Front-batched streaming loads (MLP=4, evict-first).
    float4 s0 = __ldcs(x4 + i0);
    float4 s1 = __ldcs(x4 + i0 + OFF12_V4);
    float4 s2 = __ldcs(x4 + i0 + OFF20_V4);
    float4 s3 = __ldcs(x4 + i0 + OFF20_V4 + OFF12_V4);

    float4 d0, d1, d2, d3;
    d0.x = u0.x*s0.x + u0.y*s1.x + u0.z*s2.x + u0.w*s3.x;
    d0.y = u0.x*s0.y + u0.y*s1.y + u0.z*s2.y + u0.w*s3.y;
    d0.z = u0.x*s0.z + u0.y*s1.z + u0.z*s2.z + u0.w*s3.z;
    d0.w = u0.x*s0.w + u0.y*s1.w + u0.z*s2.w + u0.w*s3.w;

    d1.x = u1.x*s0.x + u1.y*s1.x + u1.z*s2.x + u1.w*s3.x;
    d1.y = u1.x*s0.y + u1.y*s1.y + u1.z*s2.y + u1.w*s3.y;
    d1.z = u1.x*s0.z + u1.y*s1.z + u1.z*s2.z + u1.w*s3.z;
    d1.w = u1.x*s0.w + u1.y*s1.w + u1.z*s2.w + u1.w*s3.w;

    d2.x = u2.x*s0.x + u2.y*s1.x + u2.z*s2.x + u2.w*s3.x;
    d2.y = u2.x*s0.y + u2.y*s1.y + u2.z*s2.y + u2.w*s3.y;
    d2.z = u2.x*s0.z + u2.y*s1.z + u2.z*s2.z + u2.w*s3.z;
    d2.w = u2.x*s0.w + u2.y*s1.w + u2.z*s2.w + u2.w*s3.w;

    d3.x = u3.x*s0.x + u3.y*s1.x + u3.z*s2.x + u3.w*s3.x;
    d3.y = u3.x*s0.y + u3.y*s1.y + u3.z*s2.y + u3.w*s3.y;
    d3.z = u3.x*s0.z + u3.y*s1.z + u3.z*s2.z + u3.w*s3.z;
    d3.w = u3.x*s0.w + u3.y*s1.w + u3.z*s2.w + u3.w*s3.w;

    __stcs(o4 + i0,                       d0);
    __stcs(o4 + i0 + OFF12_V4,            d1);
    __stcs(o4 + i0 + OFF20_V4,            d2);
    __stcs(o4 + i0 + OFF20_V4 + OFF12_V4, d3);
}

extern "C" void kernel_launch(void* const* d_in, const int* in_sizes, int n_in,
                              void* d_out, int out_size)
{
    const float* x = (const float*)d_in[0];
    const float* U = (const float*)d_in[1];
    if (n_in >= 2 && in_sizes[0] == 16) {  // defensive: swapped order
        U = (const float*)d_in[0];
        x = (const float*)d_in[1];
    }
    float* out = (float*)d_out;

    const unsigned blocks = THREADS / BLOCK;  // 8192
    unitary_gate_kernel<<<blocks, BLOCK>>>(
        (const float4*)x, (const float4*)U, (float4*)out);
}